// round 8
// baseline (speedup 1.0000x reference)
#include <cuda_runtime.h>

#define Tn 128
#define Bn 8
#define En 256
#define Hn 512
#define G4 2048
#define NB2 128
#define NT2 256
#define WSTR 516   // 512 + pad -> 16B-aligned rows
typedef unsigned long long ull;

// ---------------- device scratch ----------------
__device__ float g_xs[Tn * Bn * G4];   // emb@Wih_s + b_s, [(t*8+b)*2048 + col]
__device__ float g_xt[Tn * Bn * G4];   // emb@Wih_t + b_t
__device__ float g_slot[2][NB2][64];   // h slices: [parity][block][32 data + pad]
__device__ unsigned int g_grp[8 * 64]; // 8 producer-group counters, 256B apart

// ---------------- helpers ----------------
__device__ __forceinline__ ull fma2(ull a, ull b, ull c) {
    ull d;
    asm("fma.rn.f32x2 %0, %1, %2, %3;" : "=l"(d) : "l"(a), "l"(b), "l"(c));
    return d;
}
__device__ __forceinline__ float2 up2(ull a) {
    float2 f;
    asm("mov.b64 {%0, %1}, %2;" : "=f"(f.x), "=f"(f.y) : "l"(a));
    return f;
}
__device__ __forceinline__ float rcpa(float x) {
    float r;
    asm("rcp.approx.f32 %0, %1;" : "=f"(r) : "f"(x));
    return r;
}
__device__ __forceinline__ float sigm(float x) {
    return rcpa(1.f + __expf(-x));
}
__device__ __forceinline__ float tanh_f(float x) {
    return 1.f - 2.f * rcpa(__expf(2.f * x) + 1.f);
}
__device__ __forceinline__ float4 ld_rel4(const float* p) {
    float4 v;
    asm volatile("ld.relaxed.gpu.global.v4.f32 {%0,%1,%2,%3}, [%4];"
                 : "=f"(v.x), "=f"(v.y), "=f"(v.z), "=f"(v.w) : "l"(p) : "memory");
    return v;
}
__device__ __forceinline__ void st_rel4(float* p, float4 v) {
    asm volatile("st.relaxed.gpu.global.v4.f32 [%0], {%1,%2,%3,%4};"
                 :: "l"(p), "f"(v.x), "f"(v.y), "f"(v.z), "f"(v.w) : "memory");
}
__device__ __forceinline__ unsigned ld_acq_u32(const unsigned* p) {
    unsigned v;
    asm volatile("ld.acquire.gpu.global.u32 %0, [%1];" : "=r"(v) : "l"(p) : "memory");
    return v;
}
__device__ __forceinline__ void grp_release(int grp) {
    asm volatile("red.release.gpu.global.add.u32 [%0], 1;"
                 :: "l"(&g_grp[grp * 64]) : "memory");
}

// ---------------- kernel 1: gathered input GEMM (both matrices via z) ----------------
__global__ void __launch_bounds__(256) input_gemm(const int* __restrict__ tokens,
                                                  const float* __restrict__ etab,
                                                  const float* __restrict__ W0,
                                                  const float* __restrict__ bias0,
                                                  const float* __restrict__ W1,
                                                  const float* __restrict__ bias1) {
    __shared__ float As[16][128];
    __shared__ float Bs[16][128];
    const int which = blockIdx.z;
    const float* W    = which ? W1 : W0;
    const float* bias = which ? bias1 : bias0;
    float* outp = which ? g_xt : g_xs;

    // reset group counters for the LSTM kernel (stream order guarantees visibility)
    if (blockIdx.x == 0 && blockIdx.y == 0 && blockIdx.z == 0 && threadIdx.x < 8)
        g_grp[threadIdx.x * 64] = 0u;

    const int m0 = blockIdx.y * 128;
    const int n0 = blockIdx.x * 128;
    const int tid = threadIdx.x;
    const int tr = tid >> 4, tc = tid & 15;

    float acc[8][8];
#pragma unroll
    for (int i = 0; i < 8; i++)
#pragma unroll
        for (int j = 0; j < 8; j++) acc[i][j] = 0.f;

    const int mA0 = tid >> 2;
    const int mA1 = (tid + 256) >> 2;
    const int kq0 = tid & 3;
    const int gm0 = m0 + mA0, gm1 = m0 + mA1;
    const long tok0 = tokens[(gm0 & 7) * Tn + (gm0 >> 3)];
    const long tok1 = tokens[(gm1 & 7) * Tn + (gm1 >> 3)];

    const int kb = tid >> 5;
    const int nq = tid & 31;

    for (int k0 = 0; k0 < En; k0 += 16) {
        float4 a0 = *(const float4*)&etab[tok0 * En + k0 + kq0 * 4];
        float4 a1 = *(const float4*)&etab[tok1 * En + k0 + kq0 * 4];
        As[kq0 * 4 + 0][mA0] = a0.x; As[kq0 * 4 + 1][mA0] = a0.y;
        As[kq0 * 4 + 2][mA0] = a0.z; As[kq0 * 4 + 3][mA0] = a0.w;
        As[kq0 * 4 + 0][mA1] = a1.x; As[kq0 * 4 + 1][mA1] = a1.y;
        As[kq0 * 4 + 2][mA1] = a1.z; As[kq0 * 4 + 3][mA1] = a1.w;

        *(float4*)&Bs[kb][nq * 4]     = *(const float4*)&W[(k0 + kb) * G4 + n0 + nq * 4];
        *(float4*)&Bs[kb + 8][nq * 4] = *(const float4*)&W[(k0 + kb + 8) * G4 + n0 + nq * 4];
        __syncthreads();

#pragma unroll
        for (int k = 0; k < 16; k++) {
            float av[8], bv[8];
            *(float4*)&av[0] = *(const float4*)&As[k][tr * 4];
            *(float4*)&av[4] = *(const float4*)&As[k][64 + tr * 4];
            *(float4*)&bv[0] = *(const float4*)&Bs[k][tc * 4];
            *(float4*)&bv[4] = *(const float4*)&Bs[k][64 + tc * 4];
#pragma unroll
            for (int i = 0; i < 8; i++)
#pragma unroll
                for (int j = 0; j < 8; j++) acc[i][j] += av[i] * bv[j];
        }
        __syncthreads();
    }

#pragma unroll
    for (int i = 0; i < 8; i++) {
        int m = m0 + ((i < 4) ? (tr * 4 + i) : (64 + tr * 4 + i - 4));
#pragma unroll
        for (int jh = 0; jh < 2; jh++) {
            int n = n0 + tc * 4 + jh * 64;
            float4 v;
            v.x = acc[i][jh * 4 + 0] + __ldg(&bias[n + 0]);
            v.y = acc[i][jh * 4 + 1] + __ldg(&bias[n + 1]);
            v.z = acc[i][jh * 4 + 2] + __ldg(&bias[n + 2]);
            v.w = acc[i][jh * 4 + 3] + __ldg(&bias[n + 3]);
            *(float4*)&outp[(long)m * G4 + n] = v;
        }
    }
}

// ---------------- kernel 2: persistent dual-LSTM, group-counter exchange ----------------
// Round r lives in buf (r&1). Init h=0 is round 1 (buf 1).
// Shared step t: consume round t+1, produce round t+2.
// Task zero-state: round 130 (buf 0). Task step t: consume 130+t, produce 131+t.
// Safety: producing round r+1 requires consuming round r, which requires every
// block produced round r, which (via its stage2 __syncthreads) requires it fully
// read round r-1 -> double buffer is never overwritten while readable.
__global__ void __launch_bounds__(NT2) lstm_kernel(const float* __restrict__ Whh_s,
                                                   const float* __restrict__ Whh_t,
                                                   const float* __restrict__ Wmh_t,
                                                   float* __restrict__ out) {
    extern __shared__ float sm[];
    float* wstage = sm;                  // [16][WSTR] weight staging (transient)
    float* hs     = wstage + 16 * WSTR;  // [8][WSTR]  current h
    float* red    = hs + 8 * WSTR;       // [16][128]  k-group partials
    float* prebuf = red + 16 * 128;      // [128]      pre-activations (c2*8+b2)
    float* hsnew  = prebuf + 128;        // [32]       new h staging

    const int tid  = threadIdx.x;
    const int bl   = blockIdx.x;
    const int w    = tid >> 5, lane = tid & 31;
    const int kg   = tid >> 4, c  = tid & 15;   // stage-1 identity
    const int c2   = tid >> 3, b2 = tid & 7;    // stage-2 identity (tid<128)
    const int col2 = (c2 >> 2) * Hn + bl * 4 + (c2 & 3);
    const int krot = (kg & 1) << 2;             // bank-phase rotation per kg-parity
    const int mygrp = bl >> 4;

    ull wreg[16];
    float creg = 0.f;                    // c-state (act warp, tid<32)

    auto stageW = [&](const float* W) {
        __syncthreads();
        for (int i = tid; i < 16 * Hn; i += NT2) {
            int cc = i & 15, k = i >> 4;
            int cl = (cc >> 2) * Hn + bl * 4 + (cc & 3);
            wstage[cc * WSTR + k] = W[(long)k * G4 + cl];
        }
        __syncthreads();
#pragma unroll
        for (int i = 0; i < 16; i++)
            wreg[i] = *(const ull*)(wstage + c * WSTR + kg * 32 + 2 * i);
    };

    // per-warp consume: poll own group counter, then load this warp's 16 slots
    auto consume = [&](int buf, unsigned round) {
        if (lane == 0) {
            const unsigned tgt = 16u * round;
            unsigned v;
            do { v = ld_acq_u32(&g_grp[w * 64]); } while (v < tgt);
        }
        __syncwarp();
        const int slot = w * 16 + (lane >> 1);      // global block id
        const float* sp = &g_slot[buf][slot][0];
        const int bb0 = (lane & 1) * 4;
#pragma unroll
        for (int i = 0; i < 4; i++) {
            float4 d = ld_rel4(sp + (bb0 + i) * 4);
            *(float4*)&hs[(bb0 + i) * WSTR + slot * 4] = d;
        }
        __syncwarp();
    };

    auto stage1 = [&]() {   // warp w reads only hs k-range [w*64, w*64+64)
        float part[8];
#pragma unroll
        for (int b = 0; b < 8; b++) {
            const float* hb = hs + b * WSTR + kg * 32;
            ull a0 = 0ull, a1 = 0ull;
#pragma unroll
            for (int kq = 0; kq < 8; kq++) {
                int kk = (kq + krot) & 7;
                ulonglong2 hv = *(const ulonglong2*)(hb + kk * 4);
                a0 = fma2(hv.x, wreg[2 * kk], a0);
                a1 = fma2(hv.y, wreg[2 * kk + 1], a1);
            }
            float2 f0 = up2(a0), f1 = up2(a1);
            part[b] = (f0.x + f1.x) + (f0.y + f1.y);
        }
        *(float4*)&red[kg * 128 + c * 8]     = make_float4(part[0], part[1], part[2], part[3]);
        *(float4*)&red[kg * 128 + c * 8 + 4] = make_float4(part[4], part[5], part[6], part[7]);
    };
    auto stage2 = [&](float xv) {   // tid<128 only
        float p = xv;
#pragma unroll
        for (int g = 0; g < 16; g++) p += red[g * 128 + tid];
        return p;
    };

    float xv = 0.f;  // prefetched x(t)

    auto do_step = [&](const float* xbase, float rcv, int t,
                       int rbuf, unsigned rround, int wbuf, float* outp) {
        consume(rbuf, rround);          // per-warp decoupled
        stage1();
        __syncthreads();                // red complete
        if (tid < 128) prebuf[tid] = stage2(xv + rcv);
        __syncthreads();                // prebuf complete; warps 1-7 may run ahead
        if (tid < 32) {
            int bb = tid >> 2, j = tid & 3;
            float iv = prebuf[(0  + j) * 8 + bb];
            float fv = prebuf[(4  + j) * 8 + bb];
            float gv = prebuf[(8  + j) * 8 + bb];
            float ov = prebuf[(12 + j) * 8 + bb];
            float cn = sigm(fv) * creg + sigm(iv) * tanh_f(gv);
            float hn = sigm(ov) * tanh_f(cn);
            creg = cn;
            hsnew[bb * 4 + j] = hn;
            __syncwarp();
            if (tid == 0) {
                float* sp = &g_slot[wbuf][bl][0];
#pragma unroll
                for (int i = 0; i < 8; i++)
                    st_rel4(sp + i * 4, *(const float4*)&hsnew[i * 4]);
                grp_release(mygrp);     // release covers the slice stores
            }
            if (tid < 8 && outp) {
                float4 v = *(const float4*)&hsnew[tid * 4];
                __stcg((float4*)&outp[(long)(tid * Tn + t) * Hn + bl * 4], v);
            }
        }
        if (tid < 128)                   // prefetch next x in the shadow
            xv = __ldcg(&xbase[(long)(((t + 1) & (Tn - 1)) * Bn + b2) * G4 + col2]);
    };

    // ---- publish round 1 (h = 0, buf 1), then stage weights ----
    if (tid == 0) {
        float* sp = &g_slot[1][bl][0];
#pragma unroll
        for (int i = 0; i < 8; i++)
            st_rel4(sp + i * 4, make_float4(0.f, 0.f, 0.f, 0.f));
        grp_release(mygrp);
    }
    stageW(Whh_s);

    // ---- shared LSTM (attention is identity: softmax over the broadcast axis
    //      of h_shared sums to 1, so Rt == h_last, constant) ----
    if (tid < 128) xv = __ldcg(&g_xs[(long)(0 * Bn + b2) * G4 + col2]);
    for (int t = 0; t < Tn; t++)
        do_step(g_xs, 0.f, t, (t + 1) & 1, (unsigned)(t + 1), t & 1, nullptr);

    // ---- h_last = round 129 (buf 1); Wmh dot uses per-warp slice of it ----
    consume(1, 129u);
    stageW(Wmh_t);                 // wreg <- Wmh slice (hs untouched)
    stage1();
    __syncthreads();
    float rcv = (tid < 128) ? stage2(0.f) : 0.f;
    stageW(Whh_t);                 // leading syncthreads protects red reads
    if (tid < 32) creg = 0.f;
    // publish task zero-state: round 130, buf 0
    if (tid == 0) {
        float* sp = &g_slot[0][bl][0];
#pragma unroll
        for (int i = 0; i < 8; i++)
            st_rel4(sp + i * 4, make_float4(0.f, 0.f, 0.f, 0.f));
        grp_release(mygrp);
    }

    // ---- task LSTM, writing output ----
    if (tid < 128) xv = __ldcg(&g_xt[(long)(0 * Bn + b2) * G4 + col2]);
    for (int t = 0; t < Tn; t++)
        do_step(g_xt, rcv, t, t & 1, (unsigned)(130 + t), (t + 1) & 1, out);
}

// ---------------- launch ----------------
extern "C" void kernel_launch(void* const* d_in, const int* in_sizes, int n_in,
                              void* d_out, int out_size) {
    const int sh = (n_in == 14) ? 0 : 1;
    const int*   tokens = (const int*)d_in[0];
    const float* etab   = (const float*)d_in[2 - sh];
    const float* Wih_s  = (const float*)d_in[3 - sh];
    const float* Whh_s  = (const float*)d_in[4 - sh];
    const float* b_s    = (const float*)d_in[5 - sh];
    const float* Wih_t  = (const float*)d_in[10 - sh];
    const float* Whh_t  = (const float*)d_in[11 - sh];
    const float* Wmh_t  = (const float*)d_in[12 - sh];
    const float* b_t    = (const float*)d_in[13 - sh];
    float* out = (float*)d_out;

    const int smem2 = (16 * WSTR + 8 * WSTR + 16 * 128 + 128 + 32) * (int)sizeof(float);
    cudaFuncSetAttribute(lstm_kernel, cudaFuncAttributeMaxDynamicSharedMemorySize, smem2);

    dim3 gg(G4 / 128, (Tn * Bn) / 128, 2);  // (16, 8, 2)
    input_gemm<<<gg, 256>>>(tokens, etab, Wih_s, b_s, Wih_t, b_t);
    lstm_kernel<<<NB2, NT2, smem2>>>(Whh_s, Whh_t, Wmh_t, out);
}

// round 9
// speedup vs baseline: 1.1112x; 1.1112x over previous
#include <cuda_runtime.h>

#define Tn 128
#define Bn 8
#define En 256
#define Hn 512
#define G4 2048
#define NB2 64          // LSTM blocks
#define NT2 512         // threads per LSTM block
#define UPB 8           // h-units per block
#define CPB 32          // gate columns per block (4 gates x 8 units)
#define WSTR 516        // 512 + pad -> 16B-aligned rows
typedef unsigned long long ull;

// ---------------- device scratch ----------------
__device__ float g_xs[Tn * Bn * G4];   // emb@Wih_s + b_s, [(t*8+b)*2048 + col]
__device__ float g_xt[Tn * Bn * G4];   // emb@Wih_t + b_t
__device__ float g_slot[2][NB2][64];   // h slices: [parity][block][8 b x 8 u]
__device__ unsigned int g_cnt;         // single monotonic counter

// ---------------- helpers ----------------
__device__ __forceinline__ ull fma2(ull a, ull b, ull c) {
    ull d;
    asm("fma.rn.f32x2 %0, %1, %2, %3;" : "=l"(d) : "l"(a), "l"(b), "l"(c));
    return d;
}
__device__ __forceinline__ float2 up2(ull a) {
    float2 f;
    asm("mov.b64 {%0, %1}, %2;" : "=f"(f.x), "=f"(f.y) : "l"(a));
    return f;
}
__device__ __forceinline__ float rcpa(float x) {
    float r;
    asm("rcp.approx.f32 %0, %1;" : "=f"(r) : "f"(x));
    return r;
}
__device__ __forceinline__ float sigm(float x)   { return rcpa(1.f + __expf(-x)); }
__device__ __forceinline__ float tanh_f(float x) { return 1.f - 2.f * rcpa(__expf(2.f * x) + 1.f); }

__device__ __forceinline__ float4 ld_rel4(const float* p) {
    float4 v;
    asm volatile("ld.relaxed.gpu.global.v4.f32 {%0,%1,%2,%3}, [%4];"
                 : "=f"(v.x), "=f"(v.y), "=f"(v.z), "=f"(v.w) : "l"(p) : "memory");
    return v;
}
__device__ __forceinline__ void st_rel4(float* p, float4 v) {
    asm volatile("st.relaxed.gpu.global.v4.f32 [%0], {%1,%2,%3,%4};"
                 :: "l"(p), "f"(v.x), "f"(v.y), "f"(v.z), "f"(v.w) : "memory");
}
__device__ __forceinline__ void bar_arrive() {
    asm volatile("red.release.gpu.global.add.u32 [%0], 1;" :: "l"(&g_cnt) : "memory");
}
__device__ __forceinline__ void bar_poll(unsigned target) {
    unsigned v;
    do {
        asm volatile("ld.relaxed.gpu.global.u32 %0, [%1];"
                     : "=r"(v) : "l"(&g_cnt) : "memory");
    } while (v < target);
}
__device__ __forceinline__ void bar_poll_fence(unsigned target) {
    bar_poll(target);
    asm volatile("fence.acq_rel.gpu;" ::: "memory");
}

// ---------------- kernel 1: gathered input GEMM (both matrices via z) ----------------
__global__ void __launch_bounds__(256) input_gemm(const int* __restrict__ tokens,
                                                  const float* __restrict__ etab,
                                                  const float* __restrict__ W0,
                                                  const float* __restrict__ bias0,
                                                  const float* __restrict__ W1,
                                                  const float* __restrict__ bias1) {
    __shared__ float As[16][128];
    __shared__ float Bs[16][128];
    const int which = blockIdx.z;
    const float* W    = which ? W1 : W0;
    const float* bias = which ? bias1 : bias0;
    float* outp = which ? g_xt : g_xs;

    if (blockIdx.x == 0 && blockIdx.y == 0 && blockIdx.z == 0 && threadIdx.x == 0)
        g_cnt = 0u;

    const int m0 = blockIdx.y * 128;
    const int n0 = blockIdx.x * 128;
    const int tid = threadIdx.x;
    const int tr = tid >> 4, tc = tid & 15;

    float acc[8][8];
#pragma unroll
    for (int i = 0; i < 8; i++)
#pragma unroll
        for (int j = 0; j < 8; j++) acc[i][j] = 0.f;

    const int mA0 = tid >> 2;
    const int mA1 = (tid + 256) >> 2;
    const int kq0 = tid & 3;
    const int gm0 = m0 + mA0, gm1 = m0 + mA1;
    const long tok0 = tokens[(gm0 & 7) * Tn + (gm0 >> 3)];
    const long tok1 = tokens[(gm1 & 7) * Tn + (gm1 >> 3)];

    const int kb = tid >> 5;
    const int nq = tid & 31;

    for (int k0 = 0; k0 < En; k0 += 16) {
        float4 a0 = *(const float4*)&etab[tok0 * En + k0 + kq0 * 4];
        float4 a1 = *(const float4*)&etab[tok1 * En + k0 + kq0 * 4];
        As[kq0 * 4 + 0][mA0] = a0.x; As[kq0 * 4 + 1][mA0] = a0.y;
        As[kq0 * 4 + 2][mA0] = a0.z; As[kq0 * 4 + 3][mA0] = a0.w;
        As[kq0 * 4 + 0][mA1] = a1.x; As[kq0 * 4 + 1][mA1] = a1.y;
        As[kq0 * 4 + 2][mA1] = a1.z; As[kq0 * 4 + 3][mA1] = a1.w;

        *(float4*)&Bs[kb][nq * 4]     = *(const float4*)&W[(k0 + kb) * G4 + n0 + nq * 4];
        *(float4*)&Bs[kb + 8][nq * 4] = *(const float4*)&W[(k0 + kb + 8) * G4 + n0 + nq * 4];
        __syncthreads();

#pragma unroll
        for (int k = 0; k < 16; k++) {
            float av[8], bv[8];
            *(float4*)&av[0] = *(const float4*)&As[k][tr * 4];
            *(float4*)&av[4] = *(const float4*)&As[k][64 + tr * 4];
            *(float4*)&bv[0] = *(const float4*)&Bs[k][tc * 4];
            *(float4*)&bv[4] = *(const float4*)&Bs[k][64 + tc * 4];
#pragma unroll
            for (int i = 0; i < 8; i++)
#pragma unroll
                for (int j = 0; j < 8; j++) acc[i][j] += av[i] * bv[j];
        }
        __syncthreads();
    }

#pragma unroll
    for (int i = 0; i < 8; i++) {
        int m = m0 + ((i < 4) ? (tr * 4 + i) : (64 + tr * 4 + i - 4));
#pragma unroll
        for (int jh = 0; jh < 2; jh++) {
            int n = n0 + tc * 4 + jh * 64;
            float4 v;
            v.x = acc[i][jh * 4 + 0] + __ldg(&bias[n + 0]);
            v.y = acc[i][jh * 4 + 1] + __ldg(&bias[n + 1]);
            v.z = acc[i][jh * 4 + 2] + __ldg(&bias[n + 2]);
            v.w = acc[i][jh * 4 + 3] + __ldg(&bias[n + 3]);
            *(float4*)&outp[(long)m * G4 + n] = v;
        }
    }
}

// ---------------- kernel 2: persistent dual-LSTM, 64 blocks x 512 threads ----------------
// Block bl owns h-units [bl*8, bl*8+8) => 32 gate cols: col = g*512 + bl*8 + u.
// stage1: warp kg = tid>>5 owns k range [kg*32, kg*32+32); lane c = tid&31 owns col.
//         h LDS is a pure 32-lane broadcast; weights live in 16 ull registers.
// stage2: tid<256, b2 = tid>>5, c2 = tid&31 (conflict-free red access).
// act:    warp 0, 2 cells per thread.
__global__ void __launch_bounds__(NT2) lstm_kernel(const float* __restrict__ Whh_s,
                                                   const float* __restrict__ Whh_t,
                                                   const float* __restrict__ Wmh_t,
                                                   float* __restrict__ out) {
    extern __shared__ float sm[];
    float* wstage = sm;                   // [32][WSTR] weight staging (transient)
    float* hs     = wstage + CPB * WSTR;  // [8][WSTR]  current h
    float* red    = hs + 8 * WSTR;        // [8][512]   partials: red[b*512 + kg*32 + c]
    float* prebuf = red + 8 * 512;        // [256]      pre-activations: [b2*32 + c2]
    float* hsnew  = prebuf + 256;         // [64]       new h slice: [b*8 + u]

    const int tid = threadIdx.x;
    const int bl  = blockIdx.x;
    const int kg  = tid >> 5, c  = tid & 31;   // stage-1: warp kg, lane col c
    const int b2  = tid >> 5, c2 = tid & 31;   // stage-2 (tid<256)
    const int col2 = (c2 >> 3) * Hn + bl * UPB + (c2 & 7);

    ull wreg[16];
    float creg0 = 0.f, creg1 = 0.f;       // 2 cell states (act warp)

    auto stageW = [&](const float* W) {
        __syncthreads();
        for (int i = tid; i < CPB * Hn; i += NT2) {
            int cc = i & 31, k = i >> 5;
            int cl = (cc >> 3) * Hn + bl * UPB + (cc & 7);
            wstage[cc * WSTR + k] = W[(long)k * G4 + cl];
        }
        __syncthreads();
#pragma unroll
        for (int i = 0; i < 16; i++)
            wreg[i] = *(const ull*)(wstage + c * WSTR + kg * 32 + 2 * i);
    };

    unsigned nbar = 0;
    auto gbar = [&]() {   // cold-path barrier (acquire fence on exit)
        __syncthreads();
        nbar++;
        if (tid == 0) { bar_arrive(); bar_poll_fence((unsigned)NB2 * nbar); }
        __syncthreads();
    };

    // gather all 64 slots (4096 floats) into hs; relaxed L2 loads
    auto consume = [&](int buf) {
        const int s = tid >> 3, b = tid & 7;          // slot, batch
        const float* sp = &g_slot[buf][s][b * 8];
        float4 d0 = ld_rel4(sp);
        float4 d1 = ld_rel4(sp + 4);
        *(float4*)&hs[b * WSTR + s * 8]     = d0;
        *(float4*)&hs[b * WSTR + s * 8 + 4] = d1;
    };

    auto stage1 = [&]() {
        float part[8];
#pragma unroll
        for (int b = 0; b < 8; b++) {
            const float* hb = hs + b * WSTR + kg * 32;
            ull a0 = 0ull, a1 = 0ull;
#pragma unroll
            for (int kq = 0; kq < 8; kq++) {
                ulonglong2 hv = *(const ulonglong2*)(hb + kq * 4);
                a0 = fma2(hv.x, wreg[2 * kq], a0);
                a1 = fma2(hv.y, wreg[2 * kq + 1], a1);
            }
            float2 f0 = up2(a0), f1 = up2(a1);
            part[b] = (f0.x + f1.x) + (f0.y + f1.y);
        }
#pragma unroll
        for (int b = 0; b < 8; b++)            // coalesced, conflict-free
            red[b * 512 + kg * 32 + c] = part[b];
    };
    auto stage2 = [&](float xv) {   // tid<256
        float p = xv;
#pragma unroll
        for (int g = 0; g < 16; g++) p += red[b2 * 512 + g * 32 + c2];
        return p;
    };

    float xv = 0.f;  // prefetched x(t) (tid<256)

    auto do_step = [&](const float* xbase, float rcv, int t,
                       int rbuf, int wbuf, float* outp, bool dobar) {
        consume(rbuf);
        __syncthreads();
        stage1();
        __syncthreads();
        if (tid < 256) prebuf[tid] = stage2(xv + rcv);
        __syncthreads();
        nbar++;
        if (tid < 32) {
            // 2 cells per thread: (b, u2) and (b, u2+1)
            const int b = tid >> 2, u2 = (tid & 3) * 2;
            float iv0 = prebuf[b * 32 + 0  + u2], iv1 = prebuf[b * 32 + 0  + u2 + 1];
            float fv0 = prebuf[b * 32 + 8  + u2], fv1 = prebuf[b * 32 + 8  + u2 + 1];
            float gv0 = prebuf[b * 32 + 16 + u2], gv1 = prebuf[b * 32 + 16 + u2 + 1];
            float ov0 = prebuf[b * 32 + 24 + u2], ov1 = prebuf[b * 32 + 24 + u2 + 1];
            float cn0 = sigm(fv0) * creg0 + sigm(iv0) * tanh_f(gv0);
            float cn1 = sigm(fv1) * creg1 + sigm(iv1) * tanh_f(gv1);
            float hn0 = sigm(ov0) * tanh_f(cn0);
            float hn1 = sigm(ov1) * tanh_f(cn1);
            creg0 = cn0; creg1 = cn1;
            hsnew[b * 8 + u2]     = hn0;
            hsnew[b * 8 + u2 + 1] = hn1;
            __syncwarp();
            if (tid < 8) {   // publish 256B slice, then one release
                float4 v0 = *(const float4*)&hsnew[tid * 8];
                float4 v1 = *(const float4*)&hsnew[tid * 8 + 4];
                float* sp = &g_slot[wbuf][bl][tid * 8];
                st_rel4(sp, v0);
                st_rel4(sp + 4, v1);
            }
            __syncwarp();
            if (tid == 0) bar_arrive();
            if (tid < 8 && outp) {   // output store off the critical path
                float4 v0 = *(const float4*)&hsnew[tid * 8];
                float4 v1 = *(const float4*)&hsnew[tid * 8 + 4];
                __stcg((float4*)&outp[(long)(tid * Tn + t) * Hn + bl * UPB], v0);
                __stcg((float4*)&outp[(long)(tid * Tn + t) * Hn + bl * UPB + 4], v1);
            }
        }
        if (tid < 256)   // prefetch next x in the shadow of the poll
            xv = __ldcg(&xbase[(long)(((t + 1) & (Tn - 1)) * Bn + (tid >> 5)) * G4 + col2]);
        if (dobar) {
            if (tid == 0) bar_poll((unsigned)NB2 * nbar);
            __syncthreads();
        }
    };

    // ---- init: h(0) = 0 into buf 0; stage shared weights ----
    if (tid < 8) {
        float* sp = &g_slot[0][bl][tid * 8];
        st_rel4(sp,     make_float4(0.f, 0.f, 0.f, 0.f));
        st_rel4(sp + 4, make_float4(0.f, 0.f, 0.f, 0.f));
    }
    __syncthreads();
    if (tid == 0) bar_arrive();
    nbar++;
    stageW(Whh_s);
    if (tid == 0) bar_poll_fence((unsigned)NB2 * nbar);
    __syncthreads();

    // ---- shared LSTM (attention is identity: softmax over the broadcast axis
    //      of h_shared sums to 1, so Rt == h_last, constant) ----
    if (tid < 256) xv = __ldcg(&g_xs[(long)(0 * Bn + b2) * G4 + col2]);
    for (int t = 0; t < Tn; t++)
        do_step(g_xs, 0.f, t, t & 1, (t & 1) ^ 1, nullptr, true);

    // h_last: step 127 (odd) wrote buf 0; all publishes already observed
    consume(0);
    __syncthreads();
    gbar();   // everyone holds h_last -> safe to overwrite buf 0

    // rc = h_last @ Wmh_t (constant across task steps)
    stageW(Wmh_t);
    stage1();
    __syncthreads();
    float rcv = (tid < 256) ? stage2(0.f) : 0.f;
    stageW(Whh_t);   // leading syncthreads protects red reads above
    creg0 = creg1 = 0.f;
    // publish task zero-state into buf 0
    if (tid < 8) {
        float* sp = &g_slot[0][bl][tid * 8];
        st_rel4(sp,     make_float4(0.f, 0.f, 0.f, 0.f));
        st_rel4(sp + 4, make_float4(0.f, 0.f, 0.f, 0.f));
    }
    __syncthreads();
    nbar++;
    if (tid == 0) { bar_arrive(); bar_poll((unsigned)NB2 * nbar); }
    __syncthreads();

    // ---- task LSTM, writing output ----
    if (tid < 256) xv = __ldcg(&g_xt[(long)(0 * Bn + b2) * G4 + col2]);
    for (int t = 0; t < Tn; t++)
        do_step(g_xt, rcv, t, t & 1, (t & 1) ^ 1, out, t != Tn - 1);
}

// ---------------- launch ----------------
extern "C" void kernel_launch(void* const* d_in, const int* in_sizes, int n_in,
                              void* d_out, int out_size) {
    const int sh = (n_in == 14) ? 0 : 1;
    const int*   tokens = (const int*)d_in[0];
    const float* etab   = (const float*)d_in[2 - sh];
    const float* Wih_s  = (const float*)d_in[3 - sh];
    const float* Whh_s  = (const float*)d_in[4 - sh];
    const float* b_s    = (const float*)d_in[5 - sh];
    const float* Wih_t  = (const float*)d_in[10 - sh];
    const float* Whh_t  = (const float*)d_in[11 - sh];
    const float* Wmh_t  = (const float*)d_in[12 - sh];
    const float* b_t    = (const float*)d_in[13 - sh];
    float* out = (float*)d_out;

    const int smem2 = (CPB * WSTR + 8 * WSTR + 8 * 512 + 256 + 64) * (int)sizeof(float);
    cudaFuncSetAttribute(lstm_kernel, cudaFuncAttributeMaxDynamicSharedMemorySize, smem2);

    dim3 gg(G4 / 128, (Tn * Bn) / 128, 2);  // (16, 8, 2)
    input_gemm<<<gg, 256>>>(tokens, etab, Wih_s, b_s, Wih_t, b_t);
    lstm_kernel<<<NB2, NT2, smem2>>>(Whh_s, Whh_t, Wmh_t, out);
}